// round 8
// baseline (speedup 1.0000x reference)
#include <cuda_runtime.h>
#include <cuda_bf16.h>
#include <math.h>
#include <stdint.h>

// Problem constants
#define B_    128
#define F_    1024
#define D_IN  128
#define H1_   512
#define H2_   512
#define E_    256
#define H_    256
#define NSH   5
#define MROWS (B_ * F_)   // 131072

// ---------------- scratch (device globals; no allocation allowed) ----------
__device__ __nv_bfloat16 g_sth[(size_t)MROWS * D_IN];
__device__ __nv_bfloat16 g_stl[(size_t)MROWS * D_IN];
__device__ __nv_bfloat16 g_h1h[(size_t)MROWS * H1_];
__device__ __nv_bfloat16 g_h1l[(size_t)MROWS * H1_];
__device__ __nv_bfloat16 g_h2h[(size_t)MROWS * H2_];
__device__ __nv_bfloat16 g_h2l[(size_t)MROWS * H2_];
__device__ __nv_bfloat16 g_w1h[H1_ * D_IN], g_w1l[H1_ * D_IN];
__device__ __nv_bfloat16 g_w2h[H2_ * H1_],  g_w2l[H2_ * H1_];
__device__ __nv_bfloat16 g_w3h[E_ * H2_],   g_w3l[E_ * H2_];
__device__ float g_emb[(size_t)MROWS * E_];   // 134 MB

// ===================== low-level helpers ===================================
__device__ __forceinline__ uint32_t smem_u32(const void* p) {
    uint32_t a;
    asm("{ .reg .u64 t; cvta.to.shared.u64 t, %1; cvt.u32.u64 %0, t; }"
        : "=r"(a) : "l"(p));
    return a;
}

__device__ __forceinline__ void cp_async16(uint32_t dst, const void* src) {
    asm volatile("cp.async.cg.shared.global [%0], [%1], 16;\n"
                 :: "r"(dst), "l"(src));
}
#define CP_COMMIT() asm volatile("cp.async.commit_group;\n" ::: "memory")
#define CP_WAIT1()  asm volatile("cp.async.wait_group 1;\n" ::: "memory")
#define CP_WAIT0()  asm volatile("cp.async.wait_group 0;\n" ::: "memory")

__device__ __forceinline__ void ldsm4(uint32_t* r, uint32_t addr) {
    asm volatile("ldmatrix.sync.aligned.m8n8.x4.shared.b16 {%0,%1,%2,%3}, [%4];\n"
                 : "=r"(r[0]), "=r"(r[1]), "=r"(r[2]), "=r"(r[3]) : "r"(addr));
}

__device__ __forceinline__ void mma16816(float* d, const uint32_t* a, const uint32_t* b) {
    asm volatile(
        "mma.sync.aligned.m16n8k16.row.col.f32.bf16.bf16.f32 "
        "{%0,%1,%2,%3}, {%4,%5,%6,%7}, {%8,%9}, {%0,%1,%2,%3};\n"
        : "+f"(d[0]), "+f"(d[1]), "+f"(d[2]), "+f"(d[3])
        : "r"(a[0]), "r"(a[1]), "r"(a[2]), "r"(a[3]), "r"(b[0]), "r"(b[1]));
}

__device__ __forceinline__ uint32_t pack_bf2(__nv_bfloat16 a, __nv_bfloat16 b) {
    __nv_bfloat162 t = __halves2bfloat162(a, b);
    return reinterpret_cast<uint32_t&>(t);
}

// =================== HMMA GEMM: C = act(A @ W^T + bias) =====================
// A as bf16 hi/lo [M,K]; W as bf16 hi/lo [N,K]. D = Ah*Wh + Ah*Wl + Al*Wh.
// CTA tile 128x256, 16 warps (2x8), warp tile 64x32. BK=64, 2-stage cp.async,
// 1 CTA/SM (512 threads, 128 regs = full RF). SMEM rows = 128B with XOR
// swizzle (c16 ^ (row&7)) -> conflict-free ldmatrix, no padding.
static constexpr int TA      = 128 * 128;          // 16384 B  A tile (hi or lo)
static constexpr int TW      = 256 * 128;          // 32768 B  W tile (hi or lo)
static constexpr int OFF_AH  = 0;
static constexpr int OFF_AL  = TA;                 // 16384
static constexpr int OFF_WH  = 2 * TA;             // 32768
static constexpr int OFF_WL  = 2 * TA + TW;        // 65536
static constexpr int STAGE_B = 2 * TA + 2 * TW;    // 98304 B
static constexpr int GEMM_SM = 2 * STAGE_B;        // 196608 B

template <int ACT, int OUT_BF>
__global__ __launch_bounds__(512, 1) void gemm_mma_kernel(
    int M, int N, int K,
    const __nv_bfloat16* __restrict__ Ah, const __nv_bfloat16* __restrict__ Al,
    const __nv_bfloat16* __restrict__ Wh, const __nv_bfloat16* __restrict__ Wl,
    const float* __restrict__ bias,
    float* __restrict__ C,
    __nv_bfloat16* __restrict__ Ch, __nv_bfloat16* __restrict__ Cl)
{
    extern __shared__ char smem[];
    const uint32_t sbase = smem_u32(smem);
    const int tid  = threadIdx.x;
    const int lane = tid & 31;
    const int wid  = tid >> 5;            // 0..15
    const int m0 = blockIdx.y * 128;
    const int n0 = blockIdx.x * 256;
    const int wm = (wid & 1) * 64;        // warp m-offset
    const int wn = (wid >> 1) * 32;       // warp n-offset (0..224)

    float acc[4][4][4];
#pragma unroll
    for (int i = 0; i < 4; i++)
#pragma unroll
        for (int j = 0; j < 4; j++)
#pragma unroll
            for (int k = 0; k < 4; k++) acc[i][j][k] = 0.f;

    // ---- cp.async geometry: 12 chunks of 16B per thread per stage ----
    // global chunk id = i*512 + tid; row768 = id>>3 (0..767), c16 = id&7.
    // rows 0-127: Ah | 128-255: Al | 256-511: Wh | 512-767: Wl
    const __nv_bfloat16* gsrc[12];
    uint32_t sdst[12];
#pragma unroll
    for (int i = 0; i < 12; i++) {
        const int r768 = i * 64 + (tid >> 3);
        const int c16  = tid & 7;
        const int t    = (i < 2) ? 0 : (i < 4) ? 1 : (i < 8) ? 2 : 3;
        const int rb   = r768 - ((t == 0) ? 0 : (t == 1) ? 128 : (t == 2) ? 256 : 512);
        const __nv_bfloat16* bp = (t == 0) ? Ah : (t == 1) ? Al : (t == 2) ? Wh : Wl;
        const int grow = ((t < 2) ? m0 : n0) + rb;
        const int toff = (t == 0) ? OFF_AH : (t == 1) ? OFF_AL : (t == 2) ? OFF_WH : OFF_WL;
        gsrc[i] = bp + (size_t)grow * K + c16 * 8;
        sdst[i] = sbase + toff + rb * 128 + (((uint32_t)(c16 ^ (rb & 7))) << 4);
    }

    // ---- ldmatrix row bases (swizzle applied per k-sub on the fly) ----
    uint32_t aRow[4], aX[4];
#pragma unroll
    for (int am = 0; am < 4; am++) {
        const int r = wm + am * 16 + (lane & 15);
        aRow[am] = (uint32_t)(r * 128);
        aX[am]   = (uint32_t)(r & 7);
    }
    uint32_t bRow[2], bX[2];
#pragma unroll
    for (int pb = 0; pb < 2; pb++) {
        const int r = wn + pb * 16 + (lane & 7) + ((lane >> 1) & 8);
        bRow[pb] = (uint32_t)(r * 128);
        bX[pb]   = (uint32_t)(r & 7);
    }
    const uint32_t ac0 = (uint32_t)(lane >> 4);        // a chunk base (0/1)
    const uint32_t bc0 = (uint32_t)((lane >> 3) & 1);  // b chunk base (0/1)

    const int NC = K >> 6;   // chunks of 64

    auto prefetch = [&](int cc, int st) {
        const uint32_t so = (uint32_t)(st * STAGE_B);
        const int kk = cc * 64;
#pragma unroll
        for (int i = 0; i < 12; i++) cp_async16(sdst[i] + so, gsrc[i] + kk);
        CP_COMMIT();
    };

    prefetch(0, 0);

    for (int cc = 0; cc < NC; cc++) {
        if (cc + 1 < NC) { prefetch(cc + 1, (cc + 1) & 1); CP_WAIT1(); }
        else             { CP_WAIT0(); }
        __syncthreads();

        const uint32_t st = sbase + (cc & 1) * STAGE_B;
#pragma unroll
        for (int s = 0; s < 4; s++) {
            const uint32_t ac = ac0 + 2 * s;   // a 16B-chunk index this sub
            const uint32_t bc = bc0 + 2 * s;

            uint32_t ah[4][4];
#pragma unroll
            for (int am = 0; am < 4; am++)
                ldsm4(ah[am], st + OFF_AH + aRow[am] + ((ac ^ aX[am]) << 4));
            uint32_t b0[4][2], b1[4][2];
#pragma unroll
            for (int pb = 0; pb < 2; pb++) {
                uint32_t r[4];
                ldsm4(r, st + OFF_WH + bRow[pb] + ((bc ^ bX[pb]) << 4));
                b0[2 * pb][0] = r[0]; b0[2 * pb][1] = r[1];
                b0[2 * pb + 1][0] = r[2]; b0[2 * pb + 1][1] = r[3];
            }
#pragma unroll
            for (int pb = 0; pb < 2; pb++) {
                uint32_t r[4];
                ldsm4(r, st + OFF_WL + bRow[pb] + ((bc ^ bX[pb]) << 4));
                b1[2 * pb][0] = r[0]; b1[2 * pb][1] = r[1];
                b1[2 * pb + 1][0] = r[2]; b1[2 * pb + 1][1] = r[3];
            }

            // group 1: ah * b0
#pragma unroll
            for (int am = 0; am < 4; am++)
#pragma unroll
                for (int an = 0; an < 4; an++) mma16816(acc[am][an], ah[am], b0[an]);

            // al loads complete under group 2
            uint32_t al[4][4];
#pragma unroll
            for (int am = 0; am < 4; am++)
                ldsm4(al[am], st + OFF_AL + aRow[am] + ((ac ^ aX[am]) << 4));

            // group 2: ah * b1
#pragma unroll
            for (int am = 0; am < 4; am++)
#pragma unroll
                for (int an = 0; an < 4; an++) mma16816(acc[am][an], ah[am], b1[an]);

            // group 3: al * b0
#pragma unroll
            for (int am = 0; am < 4; am++)
#pragma unroll
                for (int an = 0; an < 4; an++) mma16816(acc[am][an], al[am], b0[an]);
        }
        __syncthreads();
    }

    // epilogue: bias (+ReLU), store fp32 or bf16 hi/lo
#pragma unroll
    for (int am = 0; am < 4; am++) {
        const int r0 = m0 + wm + am * 16 + (lane >> 2);
        const int r1 = r0 + 8;
#pragma unroll
        for (int an = 0; an < 4; an++) {
            const int col = n0 + wn + an * 8 + ((lane & 3) << 1);
            const float bz0 = __ldg(&bias[col]);
            const float bz1 = __ldg(&bias[col + 1]);
            float v00 = acc[am][an][0] + bz0;
            float v01 = acc[am][an][1] + bz1;
            float v10 = acc[am][an][2] + bz0;
            float v11 = acc[am][an][3] + bz1;
            if (ACT) {
                v00 = fmaxf(v00, 0.f); v01 = fmaxf(v01, 0.f);
                v10 = fmaxf(v10, 0.f); v11 = fmaxf(v11, 0.f);
            }
            if (OUT_BF) {
                __nv_bfloat16 h00 = __float2bfloat16(v00), h01 = __float2bfloat16(v01);
                __nv_bfloat16 h10 = __float2bfloat16(v10), h11 = __float2bfloat16(v11);
                __nv_bfloat16 l00 = __float2bfloat16(v00 - __bfloat162float(h00));
                __nv_bfloat16 l01 = __float2bfloat16(v01 - __bfloat162float(h01));
                __nv_bfloat16 l10 = __float2bfloat16(v10 - __bfloat162float(h10));
                __nv_bfloat16 l11 = __float2bfloat16(v11 - __bfloat162float(h11));
                *reinterpret_cast<uint32_t*>(&Ch[(size_t)r0 * N + col]) = pack_bf2(h00, h01);
                *reinterpret_cast<uint32_t*>(&Cl[(size_t)r0 * N + col]) = pack_bf2(l00, l01);
                *reinterpret_cast<uint32_t*>(&Ch[(size_t)r1 * N + col]) = pack_bf2(h10, h11);
                *reinterpret_cast<uint32_t*>(&Cl[(size_t)r1 * N + col]) = pack_bf2(l10, l11);
            } else {
                *reinterpret_cast<float2*>(&C[(size_t)r0 * N + col]) = make_float2(v00, v01);
                *reinterpret_cast<float2*>(&C[(size_t)r1 * N + col]) = make_float2(v10, v11);
            }
        }
    }
}

// ---------------- fp32 -> bf16 hi/lo splits --------------------------------
__device__ __forceinline__ void split4(const float* src, __nv_bfloat16* hi,
                                       __nv_bfloat16* lo, int i) {
    float4 v = *reinterpret_cast<const float4*>(src + i);
    __nv_bfloat16 h0 = __float2bfloat16(v.x), h1 = __float2bfloat16(v.y);
    __nv_bfloat16 h2 = __float2bfloat16(v.z), h3 = __float2bfloat16(v.w);
    __nv_bfloat16 l0 = __float2bfloat16(v.x - __bfloat162float(h0));
    __nv_bfloat16 l1 = __float2bfloat16(v.y - __bfloat162float(h1));
    __nv_bfloat16 l2 = __float2bfloat16(v.z - __bfloat162float(h2));
    __nv_bfloat16 l3 = __float2bfloat16(v.w - __bfloat162float(h3));
    *reinterpret_cast<uint2*>(&hi[i]) = make_uint2(pack_bf2(h0, h1), pack_bf2(h2, h3));
    *reinterpret_cast<uint2*>(&lo[i]) = make_uint2(pack_bf2(l0, l1), pack_bf2(l2, l3));
}

__global__ __launch_bounds__(256) void split_weights_kernel(
    const float* __restrict__ W1, __nv_bfloat16* __restrict__ w1h, __nv_bfloat16* __restrict__ w1l,
    const float* __restrict__ W2, __nv_bfloat16* __restrict__ w2h, __nv_bfloat16* __restrict__ w2l,
    const float* __restrict__ W3, __nv_bfloat16* __restrict__ w3h, __nv_bfloat16* __restrict__ w3l)
{
    const int N1 = H1_ * D_IN, N2 = H2_ * H1_, N3 = E_ * H2_;
    int i = (blockIdx.x * 256 + threadIdx.x) * 4;
    if (i < N1)                split4(W1, w1h, w1l, i);
    else if (i < N1 + N2)      split4(W2, w2h, w2l, i - N1);
    else if (i < N1 + N2 + N3) split4(W3, w3h, w3l, i - N1 - N2);
}

__global__ __launch_bounds__(256) void split_state_kernel(
    const float* __restrict__ src,
    __nv_bfloat16* __restrict__ hi, __nv_bfloat16* __restrict__ lo)
{
    int i = (blockIdx.x * 256 + threadIdx.x) * 4;
    split4(src, hi, lo, i);
}

// ============ fused shuffle: 5 x (online-softmax attention + LSTM) =========
// One block per batch, 1024 threads (32 warps). Single emb pass per iteration:
// warp w streams f-rows [w*32, w*32+32), maintaining flash-style (m, l, acc).
__global__ __launch_bounds__(1024) void shuffle_kernel(
    const float* __restrict__ emb, const int* __restrict__ length,
    const float* __restrict__ W_ih, const float* __restrict__ W_hh,
    const float* __restrict__ b_ih, const float* __restrict__ b_hh,
    float* __restrict__ out)
{
    const int b    = blockIdx.x;
    const int tid  = threadIdx.x;
    const int warp = tid >> 5, lane = tid & 31;

    __shared__ __align__(16) float s_q[H_];         // qt
    __shared__ __align__(16) float s_c[H_];         // ct
    __shared__ __align__(16) float s_x[E_];         // attended
    __shared__ __align__(16) float s_g[4 * H_];     // lstm gates
    __shared__ __align__(16) float s_part[32][E_ + 4];
    __shared__ float s_m[32], s_l[32], s_fac[32];
    __shared__ float s_invL;

    if (tid < H_) { s_q[tid] = 0.f; s_c[tid] = 0.f; }
    __syncthreads();

    const int len = length[b];
    const float* eb = emb + (size_t)b * F_ * E_;
    const float4* q4 = reinterpret_cast<const float4*>(s_q);
    const float4* x4 = reinterpret_cast<const float4*>(s_x);

    for (int it = 0; it < NSH; it++) {
        // ---- single-pass attention: logits + online softmax + attended ----
        float m = -INFINITY, l = 0.f;
        float4 a0 = make_float4(0.f, 0.f, 0.f, 0.f);
        float4 a1 = make_float4(0.f, 0.f, 0.f, 0.f);
        const float4 qv0 = q4[lane], qv1 = q4[lane + 32];
        const int fb = warp * 32;
#pragma unroll 2
        for (int ff = 0; ff < 32; ff++) {
            const int f = fb + ff;
            const float4* r4 = reinterpret_cast<const float4*>(eb + (size_t)f * E_);
            const float4 v0 = r4[lane], v1 = r4[lane + 32];
            float d = v0.x * qv0.x + v0.y * qv0.y + v0.z * qv0.z + v0.w * qv0.w;
            d = fmaf(v1.x, qv1.x, d); d = fmaf(v1.y, qv1.y, d);
            d = fmaf(v1.z, qv1.z, d); d = fmaf(v1.w, qv1.w, d);
#pragma unroll
            for (int o = 16; o; o >>= 1) d += __shfl_xor_sync(0xffffffffu, d, o);
            if (f < len) {
                const float mn = fmaxf(m, d);
                const float sc = expf(m - mn);    // 0 on first valid row
                const float p  = expf(d - mn);
                l = l * sc + p;
                a0.x = fmaf(a0.x, sc, p * v0.x); a0.y = fmaf(a0.y, sc, p * v0.y);
                a0.z = fmaf(a0.z, sc, p * v0.z); a0.w = fmaf(a0.w, sc, p * v0.w);
                a1.x = fmaf(a1.x, sc, p * v1.x); a1.y = fmaf(a1.y, sc, p * v1.y);
                a1.z = fmaf(a1.z, sc, p * v1.z); a1.w = fmaf(a1.w, sc, p * v1.w);
                m = mn;
            }
        }
        {
            float4* sp = reinterpret_cast<float4*>(s_part[warp]);
            sp[lane] = a0;
            sp[lane + 32] = a1;
            if (lane == 0) { s_m[warp] = m; s_l[warp] = l; }
        }
        __syncthreads();

        // ---- combine 32 warp-partials (warp 0) ----
        if (tid < 32) {
            const float mw = s_m[tid];
            float M = mw;
#pragma unroll
            for (int o = 16; o; o >>= 1) M = fmaxf(M, __shfl_xor_sync(0xffffffffu, M, o));
            const float fac = expf(mw - M);       // 0 if warp saw no valid rows
            s_fac[tid] = fac;
            float L = s_l[tid] * fac;
#pragma unroll
            for (int o = 16; o; o >>= 1) L += __shfl_xor_sync(0xffffffffu, L, o);
            if (tid == 0) s_invL = 1.f / L;
        }
        __syncthreads();

        if (tid < E_) {
            float s = 0.f;
#pragma unroll
            for (int w = 0; w < 32; w++) s = fmaf(s_part[w][tid], s_fac[w], s);
            s_x[tid] = s * s_invL;
        }
        __syncthreads();

        // ---- LSTM gates: warp per 32 rows ----
        {
            const float4 xv0 = x4[lane], xv1 = x4[lane + 32];
            const float4 qv0b = q4[lane], qv1b = q4[lane + 32];
            for (int j = warp * 32, je = j + 32; j < je; j++) {
                const float4* wi4 = reinterpret_cast<const float4*>(W_ih + (size_t)j * E_);
                const float4* wh4 = reinterpret_cast<const float4*>(W_hh + (size_t)j * H_);
                const float4 w0 = wi4[lane], w1 = wi4[lane + 32];
                const float4 h0 = wh4[lane], h1 = wh4[lane + 32];
                float d = w0.x * xv0.x + w0.y * xv0.y + w0.z * xv0.z + w0.w * xv0.w;
                d = fmaf(w1.x, xv1.x, d); d = fmaf(w1.y, xv1.y, d);
                d = fmaf(w1.z, xv1.z, d); d = fmaf(w1.w, xv1.w, d);
                d = fmaf(h0.x, qv0b.x, d); d = fmaf(h0.y, qv0b.y, d);
                d = fmaf(h0.z, qv0b.z, d); d = fmaf(h0.w, qv0b.w, d);
                d = fmaf(h1.x, qv1b.x, d); d = fmaf(h1.y, qv1b.y, d);
                d = fmaf(h1.z, qv1b.z, d); d = fmaf(h1.w, qv1b.w, d);
#pragma unroll
                for (int o = 16; o; o >>= 1) d += __shfl_xor_sync(0xffffffffu, d, o);
                if (lane == 0) s_g[j] = d + b_ih[j] + b_hh[j];
            }
        }
        __syncthreads();

        // ---- state update (gate order i, f, g, o) ----
        if (tid < H_) {
            const float gi = 1.f / (1.f + expf(-s_g[tid]));
            const float gf = 1.f / (1.f + expf(-s_g[H_ + tid]));
            const float gg = tanhf(s_g[2 * H_ + tid]);
            const float go = 1.f / (1.f + expf(-s_g[3 * H_ + tid]));
            const float c = gf * s_c[tid] + gi * gg;
            s_c[tid] = c;
            s_q[tid] = go * tanhf(c);
        }
        __syncthreads();
    }

    // ---- output: concat(attended, qt) ----
    if (tid < E_ + H_)
        out[b * (E_ + H_) + tid] = (tid < E_) ? s_x[tid] : s_q[tid - E_];
}

// ---------------- launch ----------------------------------------------------
extern "C" void kernel_launch(void* const* d_in, const int* in_sizes, int n_in,
                              void* d_out, int out_size)
{
    const float* state = (const float*)d_in[0];
    const int*   length= (const int*)  d_in[1];
    const float* W1    = (const float*)d_in[2];
    const float* b1    = (const float*)d_in[3];
    const float* W2    = (const float*)d_in[4];
    const float* b2    = (const float*)d_in[5];
    const float* W3    = (const float*)d_in[6];
    const float* b3    = (const float*)d_in[7];
    const float* W_ih  = (const float*)d_in[8];
    const float* W_hh  = (const float*)d_in[9];
    const float* b_ih  = (const float*)d_in[10];
    const float* b_hh  = (const float*)d_in[11];
    float* out = (float*)d_out;

    __nv_bfloat16 *sth, *stl, *h1h, *h1l, *h2h, *h2l;
    __nv_bfloat16 *w1h, *w1l, *w2h, *w2l, *w3h, *w3l;
    float *emb;
    cudaGetSymbolAddress((void**)&sth, g_sth);
    cudaGetSymbolAddress((void**)&stl, g_stl);
    cudaGetSymbolAddress((void**)&h1h, g_h1h);
    cudaGetSymbolAddress((void**)&h1l, g_h1l);
    cudaGetSymbolAddress((void**)&h2h, g_h2h);
    cudaGetSymbolAddress((void**)&h2l, g_h2l);
    cudaGetSymbolAddress((void**)&w1h, g_w1h);
    cudaGetSymbolAddress((void**)&w1l, g_w1l);
    cudaGetSymbolAddress((void**)&w2h, g_w2h);
    cudaGetSymbolAddress((void**)&w2l, g_w2l);
    cudaGetSymbolAddress((void**)&w3h, g_w3h);
    cudaGetSymbolAddress((void**)&w3l, g_w3l);
    cudaGetSymbolAddress((void**)&emb, g_emb);

    cudaFuncSetAttribute(gemm_mma_kernel<1, 1>,
                         cudaFuncAttributeMaxDynamicSharedMemorySize, GEMM_SM);
    cudaFuncSetAttribute(gemm_mma_kernel<0, 0>,
                         cudaFuncAttributeMaxDynamicSharedMemorySize, GEMM_SM);

    // 1: weight splits
    {
        int n = H1_ * D_IN + H2_ * H1_ + E_ * H2_;
        split_weights_kernel<<<n / 1024, 256>>>(W1, w1h, w1l, W2, w2h, w2l, W3, w3h, w3l);
    }
    // 2: state split
    split_state_kernel<<<(MROWS * D_IN) / 1024, 256>>>(state, sth, stl);

    // 3-5: embedder MLP on HMMA tensor cores (CTA tile 128x256)
    {
        dim3 g1(H1_ / 256, MROWS / 128);
        gemm_mma_kernel<1, 1><<<g1, 512, GEMM_SM>>>(
            MROWS, H1_, D_IN, sth, stl, w1h, w1l, b1, nullptr, h1h, h1l);
        dim3 g2(H2_ / 256, MROWS / 128);
        gemm_mma_kernel<1, 1><<<g2, 512, GEMM_SM>>>(
            MROWS, H2_, H1_, h1h, h1l, w2h, w2l, b2, nullptr, h2h, h2l);
        dim3 g3(E_ / 256, MROWS / 128);
        gemm_mma_kernel<0, 0><<<g3, 512, GEMM_SM>>>(
            MROWS, E_, H2_, h2h, h2l, w3h, w3l, b3, emb, nullptr, nullptr);
    }

    // 6: fused shuffle loop (online-softmax attention + LSTM x5) + output
    shuffle_kernel<<<B_, 1024>>>(emb, length, W_ih, W_hh, b_ih, b_hh, out);
}